// round 16
// baseline (speedup 1.0000x reference)
#include <cuda_runtime.h>
#include <cstdint>

// Problem constants
#define BB 8
#define TT 128
#define NTHREADS 512

// Output layout (float32, concatenated): outputs[8,128,256], seq_lengths[8],
// hidden[1,8,256], attn[8,128,128]
#define SEQ_OFF     262144
#define HID_OFF     262152
#define ATTN_OFF    264200

// Device scratch
__device__ float g_xw1[1024 * 512];          // x @ W1[:, :E]^T + b1
__device__ float g_wx[1024 * 1024];          // x @ Wih^T
__device__ float g_ep[BB][2][16][128];       // energy partials, double-buffered
__device__ float g_hp[BB][2][16][1536];      // h-projection partials [producer][u], dbl-buf
__device__ unsigned g_fhp[BB][TT][16];       // hp flags: one slot per producer CTA
__device__ unsigned g_fe2[BB][TT][16];       // EP flags: one slot per producer CTA
#define NFLAG1 (BB * TT * 16)                // 16384 per array

// ---------------- SMEM layout (float offsets) ----------------
#define OFF_WU    0        // [1536][16]  producer weight cols (u-order)    24576
#define OFF_WX    24576    // [128][68]   Wx[j][my 64 gate rows] (pitch 68)  8704
#define OFF_HPP   33280    // [16][100]   staged producer partials           1600
#define OFF_HPST  34880    // [32]   my hproj slice
#define OFF_HWST  34912    // [64]   my h@Whh rows
#define OFF_BIAS  34976    // [64]
#define OFF_WB    35040    // [128]  softmax weights (local)
#define OFF_GFIN  35168    // [64]   activated gates
#define OFF_CST   35232    // [16]   cell state
#define OFF_HST   35248    // [16]   my h chunk (for partial compute)
#define OFF_SRED  35264    // [16]   softmax-sum warp partials
#define SMEM_FLOATS 35280
#define SMEM_BYTES (SMEM_FLOATS * 4)

// ---------------- helpers ----------------
__device__ __forceinline__ float ldcv(const float* p) {
    float v; asm volatile("ld.global.cv.f32 %0, [%1];" : "=f"(v) : "l"(p)); return v;
}
__device__ __forceinline__ void st_rel1(unsigned* p) {
    asm volatile("st.release.gpu.global.u32 [%0], %1;" :: "l"(p), "r"(1u) : "memory");
}
__device__ __forceinline__ unsigned ld_acqg(const unsigned* p) {
    unsigned v;
    asm volatile("ld.acquire.gpu.global.u32 %0, [%1];" : "=r"(v) : "l"(p) : "memory");
    return v;
}
// ONE warp polls 16 contiguous producer slots (coalesced single request/iter)
__device__ __forceinline__ void pollwarp16(const unsigned* base, int lane) {
    unsigned bal;
    do {
        unsigned v = 1u;
        if (lane < 16) v = ld_acqg(base + lane);
        bal = __ballot_sync(0xffffffffu, v != 0u);
    } while (bal != 0xffffffffu);
}
__device__ __forceinline__ float wsum(float v) {
    #pragma unroll
    for (int o = 16; o > 0; o >>= 1) v += __shfl_xor_sync(0xffffffffu, v, o);
    return v;
}
// ---- 2-MUFU tanh: e = exp(2x); (e-1)/(e+1). ~1e-6 accurate ----
__device__ __forceinline__ float tanh_m(float x) {
    x = fminf(fmaxf(x, -9.f), 9.f);
    float e = __expf(2.f * x);
    return __fdividef(e - 1.f, e + 1.f);
}
__device__ __forceinline__ float sigmoid_m(float x) {
    return __fdividef(1.f, 1.f + __expf(-x));
}

// ---------------- merged precompute: both GEMMs + flag zeroing in ONE launch ----------------
// grid (16,16,2), block (16,16).
//  z==1            : g_wx  = x @ Wih^T           (by 0..15, N=1024)
//  z==0 && by<8    : g_xw1 = x @ W1[:,:E]^T + b1 (N=512)
//  z==0 && by>=8   : zero both flag arrays (128 spare CTAs x 256 thr = 32768 slots)
__global__ void precompute(const float* __restrict__ X, const float* __restrict__ W1,
                           const float* __restrict__ b1, const float* __restrict__ Wih) {
    const int tx = threadIdx.x, ty = threadIdx.y;
    const int tid = ty * 16 + tx;
    if (blockIdx.z == 0 && blockIdx.y >= 8) {
        int cta = blockIdx.x + (blockIdx.y - 8) * 16;
        int i = cta * 256 + tid;
        if (i < NFLAG1) (&g_fhp[0][0][0])[i] = 0u;
        else            (&g_fe2[0][0][0])[i - NFLAG1] = 0u;
        return;
    }
    const bool isX = (blockIdx.z == 0);
    const float* W = isX ? W1 : Wih;
    const int wstride = isX ? 512 : 256;
    __shared__ float As[64][33];
    __shared__ float Bs[64][33];
    const int m0 = blockIdx.x * 64, n0 = blockIdx.y * 64;
    float acc[4][4] = {};
    for (int kt = 0; kt < 256; kt += 32) {
        for (int idx = tid; idx < 64 * 32; idx += 256) {
            int rr = idx >> 5, kk = idx & 31;
            As[rr][kk] = X[(m0 + rr) * 256 + kt + kk];
            Bs[rr][kk] = W[(size_t)(n0 + rr) * wstride + kt + kk];
        }
        __syncthreads();
        #pragma unroll
        for (int kk = 0; kk < 32; kk++) {
            float a[4], bv[4];
            #pragma unroll
            for (int i = 0; i < 4; i++) { a[i] = As[ty*4+i][kk]; bv[i] = Bs[tx*4+i][kk]; }
            #pragma unroll
            for (int i = 0; i < 4; i++)
                #pragma unroll
                for (int j = 0; j < 4; j++) acc[i][j] += a[i] * bv[j];
        }
        __syncthreads();
    }
    #pragma unroll
    for (int i = 0; i < 4; i++)
        #pragma unroll
        for (int j = 0; j < 4; j++) {
            int n = n0 + tx*4 + j, m = m0 + ty*4 + i;
            if (isX) g_xw1[(size_t)m * 512 + n] = acc[i][j] + b1[n];
            else     g_wx[(size_t)m * 1024 + n] = acc[i][j];
        }
}

// ---------------- persistent recurrence: 128 CTAs, projection-partial exchange ----------------
__global__ void __launch_bounds__(NTHREADS, 1)
lstm_attn(const float* __restrict__ x, const int* __restrict__ seqlen,
          const float* __restrict__ W1, const float* __restrict__ W2,
          const float* __restrict__ b2w, const float* __restrict__ Whh,
          const float* __restrict__ bih, const float* __restrict__ bhh,
          float* __restrict__ out) {
    extern __shared__ float sm[];
    const int tid = threadIdx.x;
    const int w = tid >> 5, lane = tid & 31;
    const int r = blockIdx.x & 15;
    const int b = blockIdx.x >> 4;
    const int len = seqlen[b];
    const float b2v = b2w[0];

    // ---- prologue: WU = weight columns [16r,16r+16) for all 1536 u-rows ----
    // u -> (c=u/96, off=u%96): off<32 -> W1h row 32c+off; else q=off-32:
    //   gate=q>>4, ii=q&15 -> Whh row gate*256+16c+ii.
    for (int idx = tid; idx < 1536 * 16; idx += NTHREADS) {
        int u = idx >> 4, i = idx & 15;
        int c = u / 96, off = u - 96 * c;
        float v;
        if (off < 32) {
            v = W1[(size_t)(32 * c + off) * 512 + 256 + 16 * r + i];
        } else {
            int q = off - 32, gate = q >> 4, ii = q & 15;
            v = Whh[(size_t)(gate * 256 + 16 * c + ii) * 256 + 16 * r + i];
        }
        sm[OFF_WU + u * 16 + i] = v;
    }
    for (int idx = tid; idx < 128 * 64; idx += NTHREADS) {          // Wx[j][my 64 rows], pitch 68
        int j = idx >> 6, q = idx & 63;
        sm[OFF_WX + j * 68 + q] =
            g_wx[(size_t)(b * 128 + j) * 1024 + ((q >> 4) << 8) + 16 * r + (q & 15)];
    }
    if (tid < 64) {
        int gate = tid >> 4, i = tid & 15;
        int row = gate * 256 + 16 * r + i;
        sm[OFF_BIAS + tid] = bih[row] + bhh[row];
        sm[OFF_HWST + tid] = 0.f;                      // t=0: h=0
    }
    if (tid < 32) sm[OFF_HPST + tid] = 0.f;
    if (tid < 16) sm[OFF_CST + tid] = 0.f;
    if (r == 0 && tid == 0) out[SEQ_OFF + b] = (float)len;

    // per-thread loop-invariant registers: my 8 xw1 values and 8 W2 values
    const int jE = tid >> 2, qE = tid & 3;
    float xwr[8], w2r[8];
    {
        const float* src = g_xw1 + (size_t)(b * 128 + jE) * 512 + 32 * r + qE * 8;
        const float* w2s = W2 + 32 * r + qE * 8;
        #pragma unroll
        for (int i = 0; i < 8; i++) { xwr[i] = src[i]; w2r[i] = w2s[i]; }
    }
    __syncthreads();

    for (int t = 0; t < TT; t++) {
        const int slot = t & 1;
        const bool active = t < len;

        // ---- hp phase (t>=1): poll; stage 16x96 partials; reduce -> HPST/HWST ----
        if (t > 0) {
            if (w == 0) pollwarp16(&g_fhp[b][t - 1][0], lane);
            __syncthreads();                           // doorbell A
            {   // warp w stages producer w's 96 values for my u-range
                const float* src = &g_hp[b][slot][w][96 * r];
                float v0 = ldcv(src + lane);
                float v1 = ldcv(src + 32 + lane);
                float v2 = ldcv(src + 64 + lane);
                sm[OFF_HPP + w * 100 + lane]      = v0;
                sm[OFF_HPP + w * 100 + 32 + lane] = v1;
                sm[OFF_HPP + w * 100 + 64 + lane] = v2;
            }
            __syncthreads();
            if (tid < 384) {                           // 96 rows x 4 threads: 16-way reduce
                int row = tid >> 2, g = tid & 3;
                float s = sm[OFF_HPP + (4*g + 0) * 100 + row]
                        + sm[OFF_HPP + (4*g + 1) * 100 + row]
                        + sm[OFF_HPP + (4*g + 2) * 100 + row]
                        + sm[OFF_HPP + (4*g + 3) * 100 + row];
                s += __shfl_xor_sync(0xffffffffu, s, 1);
                s += __shfl_xor_sync(0xffffffffu, s, 2);
                if (g == 0) {
                    if (row < 32) sm[OFF_HPST + row] = s;
                    else          sm[OFF_HWST + row - 32] = s;
                }
            }
        }
        __syncthreads();   // bar1: HPST/HWST ready

        // ---- P2: energy partials (8 tanh/thread) -> g_ep; release my slot ----
        {
            const float4* hp4 = (const float4*)(sm + OFF_HPST + qE * 8);
            float4 hpa = hp4[0], hpb = hp4[1];
            const float hp[8] = {hpa.x, hpa.y, hpa.z, hpa.w, hpb.x, hpb.y, hpb.z, hpb.w};
            float acc = 0.f;
            #pragma unroll
            for (int i = 0; i < 8; i++)
                acc = fmaf(tanh_m(xwr[i] + hp[i]), w2r[i], acc);
            acc += __shfl_xor_sync(0xffffffffu, acc, 1);
            acc += __shfl_xor_sync(0xffffffffu, acc, 2);
            if (qE == 0) g_ep[b][slot][r][jE] = acc;
        }
        __syncthreads();   // bar2: EP stores happen-before release
        if (tid == 0) st_rel1(&g_fe2[b][t][r]);
        if (w == 0) pollwarp16(&g_fe2[b][t][0], lane);
        __syncthreads();   // doorbell B: EP visible

        // ---- P3: read EP (cv); softmax ----
        float ex = 0.f;
        {
            const float* epb = &g_ep[b][slot][0][0];
            float s = ldcv(epb + (4*qE + 0) * 128 + jE) + ldcv(epb + (4*qE + 1) * 128 + jE)
                    + ldcv(epb + (4*qE + 2) * 128 + jE) + ldcv(epb + (4*qE + 3) * 128 + jE);
            s += __shfl_xor_sync(0xffffffffu, s, 1);
            s += __shfl_xor_sync(0xffffffffu, s, 2);
            if (qE == 0)
                ex = (jE < len) ? __expf(tanh_m(s + b2v)) : 0.f;  // energies in [-1,1]
        }
        float wp = wsum(ex);
        if (lane == 0) sm[OFF_SRED + w] = wp;
        __syncthreads();   // bar3: SRED ready
        {
            const float4* sr = (const float4*)(sm + OFF_SRED);
            float4 a = sr[0], c = sr[1], d = sr[2], e4 = sr[3];
            float S = (a.x+a.y+a.z+a.w) + (c.x+c.y+c.z+c.w)
                    + (d.x+d.y+d.z+d.w) + (e4.x+e4.y+e4.z+e4.w);
            float Sinv = __fdividef(1.f, S);
            if (qE == 0) {
                float wv = active ? ex * Sinv : 0.f;
                sm[OFF_WB + jE] = wv;
                if ((jE >> 3) == r)
                    out[ATTN_OFF + (size_t)(b * 128 + t) * 128 + jE] = wv;
            }
        }
        __syncthreads();   // bar4: WB ready

        // ---- P4: gates from Wx: row q = tid>>3, jq = tid&7 ----
        {
            int q = tid >> 3, jq = tid & 7;
            const float* wx = sm + OFF_WX + q;
            float acc = 0.f;
            #pragma unroll
            for (int jj = 0; jj < 16; jj++) {
                int j = jq + 8 * jj;
                acc = fmaf(sm[OFF_WB + j], wx[j * 68], acc);
            }
            acc += __shfl_xor_sync(0xffffffffu, acc, 1);
            acc += __shfl_xor_sync(0xffffffffu, acc, 2);
            acc += __shfl_xor_sync(0xffffffffu, acc, 4);
            if (jq == 0) {
                acc += sm[OFF_HWST + q] + sm[OFF_BIAS + q];
                sm[OFF_GFIN + q] = ((q >> 4) == 2) ? tanh_m(acc) : sigmoid_m(acc);
            }
        }
        __syncthreads();   // bar5: GFIN ready

        // ---- P5 (warp 0): LSTM update -> HST ----
        if (tid < 16) {
            float c = sm[OFF_GFIN + 16 + tid] * sm[OFF_CST + tid]
                    + sm[OFF_GFIN + tid] * sm[OFF_GFIN + 32 + tid];
            sm[OFF_CST + tid] = c;
            float hn = sm[OFF_GFIN + 48 + tid] * tanh_m(c);
            sm[OFF_HST + tid] = hn;
            out[(size_t)(b * 128 + t) * 256 + 16 * r + tid] = active ? hn : 0.f;
            if (t == len - 1) out[HID_OFF + b * 256 + 16 * r + tid] = hn;
        }
        __syncthreads();   // bar6: HST ready

        // ---- P6: projection partials for t+1 (all threads); publish; release ----
        if (t < TT - 1) {
            float hreg[16];
            {
                const float4* h4 = (const float4*)(sm + OFF_HST);
                float4 a = h4[0], c = h4[1], d = h4[2], e4 = h4[3];
                hreg[0]=a.x; hreg[1]=a.y; hreg[2]=a.z; hreg[3]=a.w;
                hreg[4]=c.x; hreg[5]=c.y; hreg[6]=c.z; hreg[7]=c.w;
                hreg[8]=d.x; hreg[9]=d.y; hreg[10]=d.z; hreg[11]=d.w;
                hreg[12]=e4.x; hreg[13]=e4.y; hreg[14]=e4.z; hreg[15]=e4.w;
            }
            float* dst = &g_hp[b][(t + 1) & 1][r][0];
            #pragma unroll
            for (int m = 0; m < 3; m++) {
                int u = tid + 512 * m;
                const float* wu = sm + OFF_WU + u * 16;
                float a = 0.f;
                #pragma unroll
                for (int i = 0; i < 16; i++) a = fmaf(wu[i], hreg[i], a);
                dst[u] = a;
            }
            __syncthreads();   // bar7: partial stores happen-before release
            if (tid == 0) st_rel1(&g_fhp[b][t][r]);
        }
        // no trailing bar: warps gate on next step's doorbells
    }
}

// ---------------- host launch ----------------
extern "C" void kernel_launch(void* const* d_in, const int* in_sizes, int n_in,
                              void* d_out, int out_size) {
    const float* x   = (const float*)d_in[0];
    const int*   sl  = (const int*)  d_in[1];
    const float* W1  = (const float*)d_in[2];
    const float* b1  = (const float*)d_in[3];
    const float* W2  = (const float*)d_in[4];
    const float* b2  = (const float*)d_in[5];
    const float* Wih = (const float*)d_in[6];
    const float* Whh = (const float*)d_in[7];
    const float* bih = (const float*)d_in[8];
    const float* bhh = (const float*)d_in[9];
    float* out = (float*)d_out;

    // ONE precompute launch: xw1 GEMM + wx GEMM + flag zeroing
    precompute<<<dim3(16, 16, 2), dim3(16, 16)>>>(x, W1, b1, Wih);

    cudaFuncSetAttribute(lstm_attn, cudaFuncAttributeMaxDynamicSharedMemorySize, SMEM_BYTES);
    lstm_attn<<<BB * 16, NTHREADS, SMEM_BYTES>>>(x, sl, W1, W2, b2, Whh, bih, bhh, out);
}